// round 2
// baseline (speedup 1.0000x reference)
#include <cuda_runtime.h>
#include <cstdint>

// Problem constants (fixed by the dataset)
#define MAX_NODES 100000
#define IN_C  32
#define HID_C 64
#define OUT_C 32

// Scratch: __device__ globals (allocation-free rule)
__device__ __align__(16) float g_agg1[MAX_NODES * IN_C];    // 12.8 MB
__device__ __align__(16) float g_h   [MAX_NODES * HID_C];   // 25.6 MB
__device__ __align__(16) float g_agg2[MAX_NODES * HID_C];   // 25.6 MB
__device__               float g_cnt [MAX_NODES];           // 0.4 MB

// ---------------------------------------------------------------------------
// Scatter-add x[src] -> agg[dst], C=32. 8 lanes per edge, float4 per lane.
// Lane 0 also bumps the degree counter (counted once, reused by layer 2).
// edge_index is int32: ei[0:E] = src, ei[E:2E] = dst.
// ---------------------------------------------------------------------------
__global__ void scatter_c32(const float* __restrict__ x,
                            const int* __restrict__ ei,
                            float* __restrict__ agg,
                            float* __restrict__ cnt,
                            int n_edges)
{
    long long t = (long long)blockIdx.x * blockDim.x + threadIdx.x;
    int e    = (int)(t >> 3);
    int lane = (int)(t & 7);
    if (e >= n_edges) return;

    int src = ei[e];
    int dst = ei[n_edges + e];

    if (lane == 0) atomicAdd(&cnt[dst], 1.0f);

    float4 v = *(const float4*)(x + (long long)src * IN_C + lane * 4);
    atomicAdd((float4*)(agg + (long long)dst * IN_C + lane * 4), v);
}

// ---------------------------------------------------------------------------
// Scatter-add h[src] -> agg[dst], C=64. 16 lanes per edge, float4 per lane.
// ---------------------------------------------------------------------------
__global__ void scatter_c64(const float* __restrict__ h,
                            const int* __restrict__ ei,
                            float* __restrict__ agg,
                            int n_edges)
{
    long long t = (long long)blockIdx.x * blockDim.x + threadIdx.x;
    int e    = (int)(t >> 4);
    int lane = (int)(t & 15);
    if (e >= n_edges) return;

    int src = ei[e];
    int dst = ei[n_edges + e];

    float4 v = *(const float4*)(h + (long long)src * HID_C + lane * 4);
    atomicAdd((float4*)(agg + (long long)dst * HID_C + lane * 4), v);
}

// ---------------------------------------------------------------------------
// Fused per-node transform: out[n,c] = act( (agg[n]/max(cnt,1)) @ Wl + b + x[n] @ Wr )
// blockDim.x = OUTC (one thread per output channel), blockDim.y nodes per block.
// Weights staged in shared (INC*OUTC*2 floats = 16 KB for both shapes here).
// ---------------------------------------------------------------------------
template <int INC, int OUTC, bool RELU>
__global__ void sage_transform(const float* __restrict__ x,
                               const float* __restrict__ agg,
                               const float* __restrict__ cnt,
                               const float* __restrict__ Wl,
                               const float* __restrict__ b,
                               const float* __restrict__ Wr,
                               float* __restrict__ out,
                               int n_nodes)
{
    __shared__ float sWl[INC * OUTC];
    __shared__ float sWr[INC * OUTC];
    for (int i = threadIdx.y * blockDim.x + threadIdx.x; i < INC * OUTC;
         i += blockDim.x * blockDim.y) {
        sWl[i] = Wl[i];
        sWr[i] = Wr[i];
    }
    __syncthreads();

    int node = blockIdx.x * blockDim.y + threadIdx.y;
    if (node >= n_nodes) return;
    int c = threadIdx.x;  // 0..OUTC-1

    float inv = 1.0f / fmaxf(cnt[node], 1.0f);
    const float* arow = agg + (long long)node * INC;
    const float* xrow = x   + (long long)node * INC;

    float acc = b[c];
#pragma unroll
    for (int k = 0; k < INC; k++) {
        acc = fmaf(arow[k] * inv, sWl[k * OUTC + c], acc);
        acc = fmaf(xrow[k],       sWr[k * OUTC + c], acc);
    }
    if (RELU) acc = fmaxf(acc, 0.0f);
    out[(long long)node * OUTC + c] = acc;
}

// ---------------------------------------------------------------------------
// Launch
// ---------------------------------------------------------------------------
extern "C" void kernel_launch(void* const* d_in, const int* in_sizes, int n_in,
                              void* d_out, int out_size)
{
    const float* x    = (const float*)d_in[0];   // [N, 32]
    const int*   ei   = (const int*)d_in[1];     // [2, E] int32 (JAX x64-disabled)
    const float* W1l  = (const float*)d_in[2];   // [32, 64]
    const float* b1   = (const float*)d_in[3];   // [64]
    const float* W1r  = (const float*)d_in[4];   // [32, 64]
    const float* W2l  = (const float*)d_in[5];   // [64, 32]
    const float* b2   = (const float*)d_in[6];   // [32]
    const float* W2r  = (const float*)d_in[7];   // [64, 32]
    float*       out  = (float*)d_out;           // [N, 32]

    const int n_nodes = in_sizes[0] / IN_C;
    const int n_edges = in_sizes[1] / 2;

    float *agg1, *h, *agg2, *cnt;
    cudaGetSymbolAddress((void**)&agg1, g_agg1);
    cudaGetSymbolAddress((void**)&h,    g_h);
    cudaGetSymbolAddress((void**)&agg2, g_agg2);
    cudaGetSymbolAddress((void**)&cnt,  g_cnt);

    // Zero scratch every call (deterministic; capture-safe memset nodes)
    cudaMemsetAsync(agg1, 0, (size_t)n_nodes * IN_C  * sizeof(float));
    cudaMemsetAsync(agg2, 0, (size_t)n_nodes * HID_C * sizeof(float));
    cudaMemsetAsync(cnt,  0, (size_t)n_nodes * sizeof(float));

    // Layer 1 aggregate: 8 lanes/edge
    {
        long long threads = (long long)n_edges * 8;
        int blocks = (int)((threads + 255) / 256);
        scatter_c32<<<blocks, 256>>>(x, ei, agg1, cnt, n_edges);
    }
    // Layer 1 transform -> h (ReLU)
    {
        dim3 blk(HID_C, 4);  // 256 threads
        int blocks = (n_nodes + 3) / 4;
        sage_transform<IN_C, HID_C, true><<<blocks, blk>>>(x, agg1, cnt, W1l, b1, W1r, h, n_nodes);
    }
    // Layer 2 aggregate: 16 lanes/edge
    {
        long long threads = (long long)n_edges * 16;
        int blocks = (int)((threads + 255) / 256);
        scatter_c64<<<blocks, 256>>>(h, ei, agg2, n_edges);
    }
    // Layer 2 transform -> out (no activation)
    {
        dim3 blk(OUT_C, 8);  // 256 threads
        int blocks = (n_nodes + 7) / 8;
        sage_transform<HID_C, OUT_C, false><<<blocks, blk>>>(h, agg2, cnt, W2l, b2, W2r, out, n_nodes);
    }
}

// round 3
// speedup vs baseline: 1.6758x; 1.6758x over previous
#include <cuda_runtime.h>
#include <cstdint>

// Problem constants (fixed by the dataset)
#define MAX_NODES 100000
#define IN_C  32
#define HID_C 64
#define OUT_C 32

// Scratch: __device__ globals (allocation-free rule)
__device__ __align__(16) float g_agg1[MAX_NODES * IN_C];    // 12.8 MB
__device__ __align__(16) float g_h   [MAX_NODES * HID_C];   // 25.6 MB
__device__ __align__(16) float g_agg2[MAX_NODES * HID_C];   // 25.6 MB
__device__               float g_cnt [MAX_NODES];           // 0.4 MB

// ---------------------------------------------------------------------------
// Packed f32x2 helpers (Blackwell FFMA2 — 2 fp32 MACs per issue slot)
// ---------------------------------------------------------------------------
__device__ __forceinline__ void fma2(unsigned long long& d,
                                     unsigned long long a,
                                     unsigned long long b)
{
    asm("fma.rn.f32x2 %0, %1, %2, %0;" : "+l"(d) : "l"(a), "l"(b));
}
__device__ __forceinline__ unsigned long long pack2(float v)
{
    unsigned long long r;
    asm("mov.b64 %0, {%1, %1};" : "=l"(r) : "r"(__float_as_uint(v)));
    return r;
}
__device__ __forceinline__ float2 unpack2(unsigned long long v)
{
    float2 f;
    asm("mov.b64 {%0, %1}, %2;" : "=f"(f.x), "=f"(f.y) : "l"(v));
    return f;
}

// ---------------------------------------------------------------------------
// Scatter-add x[src] -> agg[dst], C=32. 8 lanes per edge, float4 per lane.
// Lane 0 also bumps the degree counter (counted once, reused by layer 2).
// edge_index is int32: ei[0:E] = src, ei[E:2E] = dst.
// ---------------------------------------------------------------------------
__global__ void scatter_c32(const float* __restrict__ x,
                            const int* __restrict__ ei,
                            float* __restrict__ agg,
                            float* __restrict__ cnt,
                            int n_edges)
{
    long long t = (long long)blockIdx.x * blockDim.x + threadIdx.x;
    int e    = (int)(t >> 3);
    int lane = (int)(t & 7);
    if (e >= n_edges) return;

    int src = __ldg(ei + e);
    int dst = __ldg(ei + n_edges + e);

    if (lane == 0) atomicAdd(&cnt[dst], 1.0f);

    float4 v = *(const float4*)(x + (long long)src * IN_C + lane * 4);
    atomicAdd((float4*)(agg + (long long)dst * IN_C + lane * 4), v);
}

// ---------------------------------------------------------------------------
// Scatter-add h[src] -> agg[dst], C=64. 16 lanes per edge, float4 per lane.
// ---------------------------------------------------------------------------
__global__ void scatter_c64(const float* __restrict__ h,
                            const int* __restrict__ ei,
                            float* __restrict__ agg,
                            int n_edges)
{
    long long t = (long long)blockIdx.x * blockDim.x + threadIdx.x;
    int e    = (int)(t >> 4);
    int lane = (int)(t & 15);
    if (e >= n_edges) return;

    int src = __ldg(ei + e);
    int dst = __ldg(ei + n_edges + e);

    float4 v = *(const float4*)(h + (long long)src * HID_C + lane * 4);
    atomicAdd((float4*)(agg + (long long)dst * HID_C + lane * 4), v);
}

// ---------------------------------------------------------------------------
// Fused per-node transform: out[n,:] = act( (agg[n]/max(cnt,1)) @ Wl + b + x[n] @ Wr )
// One NODE per thread. All OUTC accumulators live in registers as f32x2 pairs.
// Weight row k is identical across the warp -> LDS.128 broadcast (conflict-free).
// FFMA2 gives 2 MACs/slot; per k: OUTC/4 LDS.128 + OUTC/2 FFMA2 (issue ratio 1:2).
// ---------------------------------------------------------------------------
template <int INC, int OUTC, bool RELU>
__global__ __launch_bounds__(256)
void sage_transform(const float* __restrict__ x,
                    const float* __restrict__ agg,
                    const float* __restrict__ cnt,
                    const float* __restrict__ Wl,
                    const float* __restrict__ b,
                    const float* __restrict__ Wr,
                    float* __restrict__ out,
                    int n_nodes)
{
    __shared__ __align__(16) float sWl[INC * OUTC];
    __shared__ __align__(16) float sWr[INC * OUTC];
    __shared__ float sB[OUTC];

    for (int i = threadIdx.x * 4; i < INC * OUTC; i += 256 * 4) {
        *(float4*)&sWl[i] = *(const float4*)&Wl[i];
        *(float4*)&sWr[i] = *(const float4*)&Wr[i];
    }
    if (threadIdx.x < OUTC) sB[threadIdx.x] = b[threadIdx.x];
    __syncthreads();

    int node = blockIdx.x * 256 + threadIdx.x;
    if (node >= n_nodes) return;

    float inv = 1.0f / fmaxf(cnt[node], 1.0f);

    unsigned long long acc[OUTC / 2];
#pragma unroll
    for (int i = 0; i < OUTC / 2; i++) acc[i] = 0ull;

    // Pass 1: (agg/cnt) @ Wl
    {
        const float4* arow = (const float4*)(agg + (long long)node * INC);
#pragma unroll
        for (int kc = 0; kc < INC / 4; kc++) {
            float4 a4 = arow[kc];
            float av[4] = {a4.x * inv, a4.y * inv, a4.z * inv, a4.w * inv};
#pragma unroll
            for (int j = 0; j < 4; j++) {
                unsigned long long av2 = pack2(av[j]);
                const int k = kc * 4 + j;
#pragma unroll
                for (int c = 0; c < OUTC; c += 4) {
                    ulonglong2 w2 = *(const ulonglong2*)&sWl[k * OUTC + c];
                    fma2(acc[c / 2],     av2, w2.x);
                    fma2(acc[c / 2 + 1], av2, w2.y);
                }
            }
        }
    }
    // Pass 2: x @ Wr
    {
        const float4* xrow = (const float4*)(x + (long long)node * INC);
#pragma unroll
        for (int kc = 0; kc < INC / 4; kc++) {
            float4 a4 = xrow[kc];
            float av[4] = {a4.x, a4.y, a4.z, a4.w};
#pragma unroll
            for (int j = 0; j < 4; j++) {
                unsigned long long av2 = pack2(av[j]);
                const int k = kc * 4 + j;
#pragma unroll
                for (int c = 0; c < OUTC; c += 4) {
                    ulonglong2 w2 = *(const ulonglong2*)&sWr[k * OUTC + c];
                    fma2(acc[c / 2],     av2, w2.x);
                    fma2(acc[c / 2 + 1], av2, w2.y);
                }
            }
        }
    }

    // Epilogue: + bias, optional ReLU, float4 stores
    float* orow = out + (long long)node * OUTC;
#pragma unroll
    for (int c = 0; c < OUTC; c += 4) {
        float2 p0 = unpack2(acc[c / 2]);
        float2 p1 = unpack2(acc[c / 2 + 1]);
        float4 o;
        o.x = p0.x + sB[c + 0];
        o.y = p0.y + sB[c + 1];
        o.z = p1.x + sB[c + 2];
        o.w = p1.y + sB[c + 3];
        if (RELU) {
            o.x = fmaxf(o.x, 0.0f); o.y = fmaxf(o.y, 0.0f);
            o.z = fmaxf(o.z, 0.0f); o.w = fmaxf(o.w, 0.0f);
        }
        *(float4*)&orow[c] = o;
    }
}

// ---------------------------------------------------------------------------
// Launch
// ---------------------------------------------------------------------------
extern "C" void kernel_launch(void* const* d_in, const int* in_sizes, int n_in,
                              void* d_out, int out_size)
{
    const float* x    = (const float*)d_in[0];   // [N, 32]
    const int*   ei   = (const int*)d_in[1];     // [2, E] int32
    const float* W1l  = (const float*)d_in[2];   // [32, 64]
    const float* b1   = (const float*)d_in[3];   // [64]
    const float* W1r  = (const float*)d_in[4];   // [32, 64]
    const float* W2l  = (const float*)d_in[5];   // [64, 32]
    const float* b2   = (const float*)d_in[6];   // [32]
    const float* W2r  = (const float*)d_in[7];   // [64, 32]
    float*       out  = (float*)d_out;           // [N, 32]

    const int n_nodes = in_sizes[0] / IN_C;
    const int n_edges = in_sizes[1] / 2;

    float *agg1, *h, *agg2, *cnt;
    cudaGetSymbolAddress((void**)&agg1, g_agg1);
    cudaGetSymbolAddress((void**)&h,    g_h);
    cudaGetSymbolAddress((void**)&agg2, g_agg2);
    cudaGetSymbolAddress((void**)&cnt,  g_cnt);

    cudaMemsetAsync(agg1, 0, (size_t)n_nodes * IN_C  * sizeof(float));
    cudaMemsetAsync(agg2, 0, (size_t)n_nodes * HID_C * sizeof(float));
    cudaMemsetAsync(cnt,  0, (size_t)n_nodes * sizeof(float));

    // Layer 1 aggregate: 8 lanes/edge
    {
        long long threads = (long long)n_edges * 8;
        int blocks = (int)((threads + 255) / 256);
        scatter_c32<<<blocks, 256>>>(x, ei, agg1, cnt, n_edges);
    }
    // Layer 1 transform -> h (ReLU)
    {
        int blocks = (n_nodes + 255) / 256;
        sage_transform<IN_C, HID_C, true><<<blocks, 256>>>(x, agg1, cnt, W1l, b1, W1r, h, n_nodes);
    }
    // Layer 2 aggregate: 16 lanes/edge
    {
        long long threads = (long long)n_edges * 16;
        int blocks = (int)((threads + 255) / 256);
        scatter_c64<<<blocks, 256>>>(h, ei, agg2, n_edges);
    }
    // Layer 2 transform -> out (no activation)
    {
        int blocks = (n_nodes + 255) / 256;
        sage_transform<HID_C, OUT_C, false><<<blocks, 256>>>(h, agg2, cnt, W2l, b2, W2r, out, n_nodes);
    }
}

// round 4
// speedup vs baseline: 1.9749x; 1.1785x over previous
#include <cuda_runtime.h>
#include <cstdint>

#define MAX_NODES 100000
#define IN_C  32
#define HID_C 64
#define OUT_C 32

// Scratch (__device__ globals: allocation-free rule)
__device__ __align__(16) float g_agg1[MAX_NODES * IN_C];    // 12.8 MB
__device__ __align__(16) float g_h   [MAX_NODES * HID_C];   // 25.6 MB
__device__ __align__(16) float g_hw  [MAX_NODES * OUT_C];   // 12.8 MB  h @ W2_l
__device__ __align__(16) float g_agg2[MAX_NODES * OUT_C];   // 12.8 MB  (32-dim now!)
__device__               float g_cnt [MAX_NODES];           // 0.4 MB

// ---------------------------------------------------------------------------
// Packed f32x2 helpers (Blackwell FFMA2)
// ---------------------------------------------------------------------------
__device__ __forceinline__ void fma2(unsigned long long& d,
                                     unsigned long long a,
                                     unsigned long long b)
{
    asm("fma.rn.f32x2 %0, %1, %2, %0;" : "+l"(d) : "l"(a), "l"(b));
}
__device__ __forceinline__ unsigned long long pack2(float v)
{
    unsigned long long r;
    asm("mov.b64 %0, {%1, %1};" : "=l"(r) : "r"(__float_as_uint(v)));
    return r;
}
__device__ __forceinline__ unsigned long long pack2f(float a, float b)
{
    unsigned long long r;
    asm("mov.b64 %0, {%1, %2};" : "=l"(r) : "f"(a), "f"(b));
    return r;
}
__device__ __forceinline__ float2 unpack2(unsigned long long v)
{
    float2 f;
    asm("mov.b64 {%0, %1}, %2;" : "=f"(f.x), "=f"(f.y) : "l"(v));
    return f;
}

// ---------------------------------------------------------------------------
// Scatter-add src rows -> agg[dst], C=32. 8 lanes/edge, float4 vector atomics.
// Optionally bumps the degree counter (layer 1 only).
// ---------------------------------------------------------------------------
template <bool COUNT>
__global__ void scatter32(const float* __restrict__ feat,
                          const int* __restrict__ ei,
                          float* __restrict__ agg,
                          float* __restrict__ cnt,
                          int n_edges)
{
    long long t = (long long)blockIdx.x * blockDim.x + threadIdx.x;
    int e    = (int)(t >> 3);
    int lane = (int)(t & 7);
    if (e >= n_edges) return;

    int src = __ldg(ei + e);
    int dst = __ldg(ei + n_edges + e);

    if (COUNT && lane == 0) atomicAdd(&cnt[dst], 1.0f);

    float4 v = *(const float4*)(feat + (long long)src * 32 + lane * 4);
    atomicAdd((float4*)(agg + (long long)dst * 32 + lane * 4), v);
}

// ---------------------------------------------------------------------------
// Layer-1 transform: h[n,:] = relu( (agg1[n]/max(cnt,1)) @ W1l + b1 + x[n] @ W1r )
// NODES=2 nodes per thread; acc in registers as f32x2; weights LDS.128 broadcast,
// each weight load feeds both nodes.
// ---------------------------------------------------------------------------
__global__ __launch_bounds__(256, 1)
void transform_l1(const float* __restrict__ x,
                  const float* __restrict__ agg,
                  const float* __restrict__ cnt,
                  const float* __restrict__ Wl,
                  const float* __restrict__ b,
                  const float* __restrict__ Wr,
                  float* __restrict__ h,
                  int n_nodes)
{
    const int INC = IN_C, OUTC = HID_C, NODES = 2;
    __shared__ __align__(16) float sWl[INC * OUTC];
    __shared__ __align__(16) float sWr[INC * OUTC];
    __shared__ float sB[OUTC];

    for (int i = threadIdx.x * 4; i < INC * OUTC; i += 256 * 4) {
        *(float4*)&sWl[i] = *(const float4*)&Wl[i];
        *(float4*)&sWr[i] = *(const float4*)&Wr[i];
    }
    if (threadIdx.x < OUTC) sB[threadIdx.x] = b[threadIdx.x];
    __syncthreads();

    int base = blockIdx.x * 256 * NODES + threadIdx.x;
    int node[NODES];
    bool valid[NODES];
#pragma unroll
    for (int i = 0; i < NODES; i++) {
        int n = base + i * 256;
        valid[i] = n < n_nodes;
        node[i] = valid[i] ? n : (n_nodes - 1);
    }

    float inv[NODES];
#pragma unroll
    for (int i = 0; i < NODES; i++) inv[i] = 1.0f / fmaxf(cnt[node[i]], 1.0f);

    unsigned long long acc[NODES][OUTC / 2];
#pragma unroll
    for (int i = 0; i < NODES; i++)
#pragma unroll
        for (int j = 0; j < OUTC / 2; j++) acc[i][j] = 0ull;

    // Pass 1: (agg/cnt) @ Wl
#pragma unroll
    for (int kc = 0; kc < INC / 4; kc++) {
        float4 a4[NODES];
#pragma unroll
        for (int i = 0; i < NODES; i++)
            a4[i] = *(const float4*)(agg + (long long)node[i] * INC + kc * 4);
#pragma unroll
        for (int j = 0; j < 4; j++) {
            unsigned long long av[NODES];
#pragma unroll
            for (int i = 0; i < NODES; i++) {
                float s = (j == 0 ? a4[i].x : j == 1 ? a4[i].y : j == 2 ? a4[i].z : a4[i].w) * inv[i];
                av[i] = pack2(s);
            }
            const int k = kc * 4 + j;
#pragma unroll
            for (int c = 0; c < OUTC; c += 4) {
                ulonglong2 w2 = *(const ulonglong2*)&sWl[k * OUTC + c];
#pragma unroll
                for (int i = 0; i < NODES; i++) {
                    fma2(acc[i][c / 2],     av[i], w2.x);
                    fma2(acc[i][c / 2 + 1], av[i], w2.y);
                }
            }
        }
    }
    // Pass 2: x @ Wr
#pragma unroll
    for (int kc = 0; kc < INC / 4; kc++) {
        float4 a4[NODES];
#pragma unroll
        for (int i = 0; i < NODES; i++)
            a4[i] = *(const float4*)(x + (long long)node[i] * INC + kc * 4);
#pragma unroll
        for (int j = 0; j < 4; j++) {
            unsigned long long av[NODES];
#pragma unroll
            for (int i = 0; i < NODES; i++) {
                float s = (j == 0 ? a4[i].x : j == 1 ? a4[i].y : j == 2 ? a4[i].z : a4[i].w);
                av[i] = pack2(s);
            }
            const int k = kc * 4 + j;
#pragma unroll
            for (int c = 0; c < OUTC; c += 4) {
                ulonglong2 w2 = *(const ulonglong2*)&sWr[k * OUTC + c];
#pragma unroll
                for (int i = 0; i < NODES; i++) {
                    fma2(acc[i][c / 2],     av[i], w2.x);
                    fma2(acc[i][c / 2 + 1], av[i], w2.y);
                }
            }
        }
    }

    // Epilogue: bias + ReLU
#pragma unroll
    for (int i = 0; i < NODES; i++) {
        if (!valid[i]) continue;
        float* orow = h + (long long)node[i] * OUTC;
#pragma unroll
        for (int c = 0; c < OUTC; c += 4) {
            float2 p0 = unpack2(acc[i][c / 2]);
            float2 p1 = unpack2(acc[i][c / 2 + 1]);
            float4 o;
            o.x = fmaxf(p0.x + sB[c + 0], 0.0f);
            o.y = fmaxf(p0.y + sB[c + 1], 0.0f);
            o.z = fmaxf(p1.x + sB[c + 2], 0.0f);
            o.w = fmaxf(p1.y + sB[c + 3], 0.0f);
            *(float4*)&orow[c] = o;
        }
    }
}

// ---------------------------------------------------------------------------
// Single GEMM (+optional agg/cnt + bias init): out[n,:] = init + in[n,:] @ W
//   INIT_AGG=false: init = 0                      (hW = h @ W2l)
//   INIT_AGG=true : init = agg[n]/max(cnt,1) + b  (out = agg2/cnt + b2 + h @ W2r)
// NODES=4 nodes per thread.
// ---------------------------------------------------------------------------
template <int INC, int OUTC, bool INIT_AGG>
__global__ __launch_bounds__(256, 1)
void gemm_add(const float* __restrict__ in,
              const float* __restrict__ W,
              const float* __restrict__ agg,
              const float* __restrict__ cnt,
              const float* __restrict__ b,
              float* __restrict__ out,
              int n_nodes)
{
    const int NODES = 4;
    __shared__ __align__(16) float sW[INC * OUTC];
    __shared__ float sB[OUTC];

    for (int i = threadIdx.x * 4; i < INC * OUTC; i += 256 * 4)
        *(float4*)&sW[i] = *(const float4*)&W[i];
    if (INIT_AGG && threadIdx.x < OUTC) sB[threadIdx.x] = b[threadIdx.x];
    __syncthreads();

    int base = blockIdx.x * 256 * NODES + threadIdx.x;
    int node[NODES];
    bool valid[NODES];
#pragma unroll
    for (int i = 0; i < NODES; i++) {
        int n = base + i * 256;
        valid[i] = n < n_nodes;
        node[i] = valid[i] ? n : (n_nodes - 1);
    }

    unsigned long long acc[NODES][OUTC / 2];
    if (INIT_AGG) {
#pragma unroll
        for (int i = 0; i < NODES; i++) {
            float inv = 1.0f / fmaxf(cnt[node[i]], 1.0f);
#pragma unroll
            for (int c = 0; c < OUTC; c += 4) {
                float4 a = *(const float4*)(agg + (long long)node[i] * OUTC + c);
                acc[i][c / 2]     = pack2f(a.x * inv + sB[c + 0], a.y * inv + sB[c + 1]);
                acc[i][c / 2 + 1] = pack2f(a.z * inv + sB[c + 2], a.w * inv + sB[c + 3]);
            }
        }
    } else {
#pragma unroll
        for (int i = 0; i < NODES; i++)
#pragma unroll
            for (int j = 0; j < OUTC / 2; j++) acc[i][j] = 0ull;
    }

#pragma unroll
    for (int kc = 0; kc < INC / 4; kc++) {
        float4 a4[NODES];
#pragma unroll
        for (int i = 0; i < NODES; i++)
            a4[i] = *(const float4*)(in + (long long)node[i] * INC + kc * 4);
#pragma unroll
        for (int j = 0; j < 4; j++) {
            unsigned long long av[NODES];
#pragma unroll
            for (int i = 0; i < NODES; i++) {
                float s = (j == 0 ? a4[i].x : j == 1 ? a4[i].y : j == 2 ? a4[i].z : a4[i].w);
                av[i] = pack2(s);
            }
            const int k = kc * 4 + j;
#pragma unroll
            for (int c = 0; c < OUTC; c += 4) {
                ulonglong2 w2 = *(const ulonglong2*)&sW[k * OUTC + c];
#pragma unroll
                for (int i = 0; i < NODES; i++) {
                    fma2(acc[i][c / 2],     av[i], w2.x);
                    fma2(acc[i][c / 2 + 1], av[i], w2.y);
                }
            }
        }
    }

#pragma unroll
    for (int i = 0; i < NODES; i++) {
        if (!valid[i]) continue;
        float* orow = out + (long long)node[i] * OUTC;
#pragma unroll
        for (int c = 0; c < OUTC; c += 4) {
            float2 p0 = unpack2(acc[i][c / 2]);
            float2 p1 = unpack2(acc[i][c / 2 + 1]);
            float4 o = {p0.x, p0.y, p1.x, p1.y};
            *(float4*)&orow[c] = o;
        }
    }
}

// ---------------------------------------------------------------------------
// Launch
// ---------------------------------------------------------------------------
extern "C" void kernel_launch(void* const* d_in, const int* in_sizes, int n_in,
                              void* d_out, int out_size)
{
    const float* x    = (const float*)d_in[0];   // [N, 32]
    const int*   ei   = (const int*)d_in[1];     // [2, E] int32
    const float* W1l  = (const float*)d_in[2];   // [32, 64]
    const float* b1   = (const float*)d_in[3];   // [64]
    const float* W1r  = (const float*)d_in[4];   // [32, 64]
    const float* W2l  = (const float*)d_in[5];   // [64, 32]
    const float* b2   = (const float*)d_in[6];   // [32]
    const float* W2r  = (const float*)d_in[7];   // [64, 32]
    float*       out  = (float*)d_out;           // [N, 32]

    const int n_nodes = in_sizes[0] / IN_C;
    const int n_edges = in_sizes[1] / 2;

    float *agg1, *h, *hw, *agg2, *cnt;
    cudaGetSymbolAddress((void**)&agg1, g_agg1);
    cudaGetSymbolAddress((void**)&h,    g_h);
    cudaGetSymbolAddress((void**)&hw,   g_hw);
    cudaGetSymbolAddress((void**)&agg2, g_agg2);
    cudaGetSymbolAddress((void**)&cnt,  g_cnt);

    cudaMemsetAsync(agg1, 0, (size_t)n_nodes * IN_C  * sizeof(float));
    cudaMemsetAsync(agg2, 0, (size_t)n_nodes * OUT_C * sizeof(float));
    cudaMemsetAsync(cnt,  0, (size_t)n_nodes * sizeof(float));

    // Layer 1 aggregate (32-dim) + degree count
    {
        long long threads = (long long)n_edges * 8;
        int blocks = (int)((threads + 255) / 256);
        scatter32<true><<<blocks, 256>>>(x, ei, agg1, cnt, n_edges);
    }
    // Layer 1 transform -> h (ReLU), 2 nodes/thread
    {
        int blocks = (n_nodes + 511) / 512;
        transform_l1<<<blocks, 256>>>(x, agg1, cnt, W1l, b1, W1r, h, n_nodes);
    }
    // Pre-projection: hW = h @ W2l  (linearity of mean => scatter 32-dim, not 64)
    {
        int blocks = (n_nodes + 1023) / 1024;
        gemm_add<HID_C, OUT_C, false><<<blocks, 256>>>(h, W2l, nullptr, nullptr, nullptr, hw, n_nodes);
    }
    // Layer 2 aggregate (32-dim)
    {
        long long threads = (long long)n_edges * 8;
        int blocks = (int)((threads + 255) / 256);
        scatter32<false><<<blocks, 256>>>(hw, ei, agg2, nullptr, n_edges);
    }
    // Layer 2 transform -> out = agg2/cnt + b2 + h @ W2r
    {
        int blocks = (n_nodes + 1023) / 1024;
        gemm_add<HID_C, OUT_C, true><<<blocks, 256>>>(h, W2r, agg2, cnt, b2, out, n_nodes);
    }
}

// round 5
// speedup vs baseline: 2.1394x; 1.0833x over previous
#include <cuda_runtime.h>
#include <cstdint>

#define MAX_NODES 100000
#define IN_C  32
#define HID_C 64
#define OUT_C 32

// Scratch (__device__ globals: allocation-free rule)
__device__ __align__(16) float g_agg1[MAX_NODES * IN_C];    // 12.8 MB
__device__ __align__(16) float g_h   [MAX_NODES * HID_C];   // 25.6 MB
__device__ __align__(16) float g_hw  [MAX_NODES * OUT_C];   // 12.8 MB  relu(h) @ W2_l
__device__ __align__(16) float g_agg2[MAX_NODES * OUT_C];   // 12.8 MB
__device__               float g_cnt [MAX_NODES];           // 0.4 MB

// ---------------------------------------------------------------------------
// Packed f32x2 helpers (Blackwell FFMA2)
// ---------------------------------------------------------------------------
__device__ __forceinline__ void fma2(unsigned long long& d,
                                     unsigned long long a,
                                     unsigned long long b)
{
    asm("fma.rn.f32x2 %0, %1, %2, %0;" : "+l"(d) : "l"(a), "l"(b));
}
__device__ __forceinline__ unsigned long long pack2(float v)
{
    unsigned long long r;
    asm("mov.b64 %0, {%1, %1};" : "=l"(r) : "r"(__float_as_uint(v)));
    return r;
}
__device__ __forceinline__ unsigned long long pack2f(float a, float b)
{
    unsigned long long r;
    asm("mov.b64 %0, {%1, %2};" : "=l"(r) : "f"(a), "f"(b));
    return r;
}
__device__ __forceinline__ float2 unpack2(unsigned long long v)
{
    float2 f;
    asm("mov.b64 {%0, %1}, %2;" : "=f"(f.x), "=f"(f.y) : "l"(v));
    return f;
}

// ---------------------------------------------------------------------------
// Warp-shuffle scatter-add, C=32. Each warp owns 32 edges: every lane loads
// its own edge's (src,dst) ONCE (coalesced), then 8 passes of 4 edges x 8
// float4 segments; indices distributed via shfl (ALU pipe, off the LSU).
// ---------------------------------------------------------------------------
template <bool COUNT>
__global__ void scatter32(const float* __restrict__ feat,
                          const int* __restrict__ ei,
                          float* __restrict__ agg,
                          float* __restrict__ cnt,
                          int n_edges)
{
    int warp = (blockIdx.x * blockDim.x + threadIdx.x) >> 5;
    int lane = threadIdx.x & 31;
    int base = warp * 32;
    if (base >= n_edges) return;

    int my_e   = base + lane;
    bool has   = my_e < n_edges;
    int e_clmp = has ? my_e : (n_edges - 1);
    int my_src = __ldg(ei + e_clmp);
    int my_dst = __ldg(ei + n_edges + e_clmp);

    if (COUNT && has) atomicAdd(&cnt[my_dst], 1.0f);

    int seg = lane & 7;   // float4 segment within the 32-float row
    int sub = lane >> 3;  // which of 4 edges this pass

#pragma unroll
    for (int pass = 0; pass < 8; pass++) {
        int eslot = pass * 4 + sub;                       // 0..31
        int src = __shfl_sync(0xffffffffu, my_src, eslot);
        int dst = __shfl_sync(0xffffffffu, my_dst, eslot);
        if (base + eslot < n_edges) {
            float4 v = *(const float4*)(feat + (long long)src * 32 + seg * 4);
            atomicAdd((float4*)(agg + (long long)dst * 32 + seg * 4), v);
        }
    }
}

// ---------------------------------------------------------------------------
// Fused layer-1 transform + pre-projection:
//   h[n,:]  = relu( (agg1[n]/max(cnt,1)) @ W1l + b1 + x[n] @ W1r )
//   hw[n,:] = h[n,:] @ W2l           (linearity of mean => 32-dim scatter)
// One node per thread; accumulators in f32x2 registers; weights in shared,
// read as LDS.128 broadcast.
// ---------------------------------------------------------------------------
__global__ __launch_bounds__(256)
void transform_l1_fused(const float* __restrict__ x,
                        const float* __restrict__ agg,
                        const float* __restrict__ cnt,
                        const float* __restrict__ Wl,
                        const float* __restrict__ b,
                        const float* __restrict__ Wr,
                        const float* __restrict__ W2l,
                        float* __restrict__ h,
                        float* __restrict__ hw,
                        int n_nodes)
{
    __shared__ __align__(16) float sWl [IN_C  * HID_C];
    __shared__ __align__(16) float sWr [IN_C  * HID_C];
    __shared__ __align__(16) float sW2l[HID_C * OUT_C];
    __shared__ float sB[HID_C];

    for (int i = threadIdx.x * 4; i < IN_C * HID_C; i += 256 * 4) {
        *(float4*)&sWl[i] = *(const float4*)&Wl[i];
        *(float4*)&sWr[i] = *(const float4*)&Wr[i];
    }
    for (int i = threadIdx.x * 4; i < HID_C * OUT_C; i += 256 * 4)
        *(float4*)&sW2l[i] = *(const float4*)&W2l[i];
    if (threadIdx.x < HID_C) sB[threadIdx.x] = b[threadIdx.x];
    __syncthreads();

    int node = blockIdx.x * 256 + threadIdx.x;
    if (node >= n_nodes) return;

    float inv = 1.0f / fmaxf(cnt[node], 1.0f);

    unsigned long long acc[HID_C / 2];
#pragma unroll
    for (int i = 0; i < HID_C / 2; i++) acc[i] = 0ull;

    // Pass 1: (agg/cnt) @ W1l
    {
        const float4* arow = (const float4*)(agg + (long long)node * IN_C);
#pragma unroll
        for (int kc = 0; kc < IN_C / 4; kc++) {
            float4 a4 = arow[kc];
            float av[4] = {a4.x * inv, a4.y * inv, a4.z * inv, a4.w * inv};
#pragma unroll
            for (int j = 0; j < 4; j++) {
                unsigned long long av2 = pack2(av[j]);
                const int k = kc * 4 + j;
#pragma unroll
                for (int c = 0; c < HID_C; c += 4) {
                    ulonglong2 w2 = *(const ulonglong2*)&sWl[k * HID_C + c];
                    fma2(acc[c / 2],     av2, w2.x);
                    fma2(acc[c / 2 + 1], av2, w2.y);
                }
            }
        }
    }
    // Pass 2: x @ W1r
    {
        const float4* xrow = (const float4*)(x + (long long)node * IN_C);
#pragma unroll
        for (int kc = 0; kc < IN_C / 4; kc++) {
            float4 a4 = xrow[kc];
            float av[4] = {a4.x, a4.y, a4.z, a4.w};
#pragma unroll
            for (int j = 0; j < 4; j++) {
                unsigned long long av2 = pack2(av[j]);
                const int k = kc * 4 + j;
#pragma unroll
                for (int c = 0; c < HID_C; c += 4) {
                    ulonglong2 w2 = *(const ulonglong2*)&sWr[k * HID_C + c];
                    fma2(acc[c / 2],     av2, w2.x);
                    fma2(acc[c / 2 + 1], av2, w2.y);
                }
            }
        }
    }

    // Epilogue 1: bias + ReLU -> keep h in registers, store to gmem
    float hval[HID_C];
    float* hrow = h + (long long)node * HID_C;
#pragma unroll
    for (int c = 0; c < HID_C; c += 4) {
        float2 p0 = unpack2(acc[c / 2]);
        float2 p1 = unpack2(acc[c / 2 + 1]);
        float4 o;
        o.x = fmaxf(p0.x + sB[c + 0], 0.0f);
        o.y = fmaxf(p0.y + sB[c + 1], 0.0f);
        o.z = fmaxf(p1.x + sB[c + 2], 0.0f);
        o.w = fmaxf(p1.y + sB[c + 3], 0.0f);
        hval[c + 0] = o.x; hval[c + 1] = o.y;
        hval[c + 2] = o.z; hval[c + 3] = o.w;
        *(float4*)&hrow[c] = o;
    }

    // Pass 3: hw = h @ W2l
    unsigned long long acc2[OUT_C / 2];
#pragma unroll
    for (int i = 0; i < OUT_C / 2; i++) acc2[i] = 0ull;
#pragma unroll
    for (int k = 0; k < HID_C; k++) {
        unsigned long long av2 = pack2(hval[k]);
#pragma unroll
        for (int c = 0; c < OUT_C; c += 4) {
            ulonglong2 w2 = *(const ulonglong2*)&sW2l[k * OUT_C + c];
            fma2(acc2[c / 2],     av2, w2.x);
            fma2(acc2[c / 2 + 1], av2, w2.y);
        }
    }
    float* hwrow = hw + (long long)node * OUT_C;
#pragma unroll
    for (int c = 0; c < OUT_C; c += 4) {
        float2 p0 = unpack2(acc2[c / 2]);
        float2 p1 = unpack2(acc2[c / 2 + 1]);
        float4 o = {p0.x, p0.y, p1.x, p1.y};
        *(float4*)&hwrow[c] = o;
    }
}

// ---------------------------------------------------------------------------
// Final transform: out[n,:] = agg2[n]/max(cnt,1) + b2 + h[n,:] @ W2r
// NODES=4 nodes per thread.
// ---------------------------------------------------------------------------
__global__ __launch_bounds__(256)
void gemm_final(const float* __restrict__ in,
                const float* __restrict__ W,
                const float* __restrict__ agg,
                const float* __restrict__ cnt,
                const float* __restrict__ b,
                float* __restrict__ out,
                int n_nodes)
{
    const int INC = HID_C, OUTC = OUT_C, NODES = 4;
    __shared__ __align__(16) float sW[INC * OUTC];
    __shared__ float sB[OUTC];

    for (int i = threadIdx.x * 4; i < INC * OUTC; i += 256 * 4)
        *(float4*)&sW[i] = *(const float4*)&W[i];
    if (threadIdx.x < OUTC) sB[threadIdx.x] = b[threadIdx.x];
    __syncthreads();

    int base = blockIdx.x * 256 * NODES + threadIdx.x;
    int node[NODES];
    bool valid[NODES];
#pragma unroll
    for (int i = 0; i < NODES; i++) {
        int n = base + i * 256;
        valid[i] = n < n_nodes;
        node[i] = valid[i] ? n : (n_nodes - 1);
    }

    unsigned long long acc[NODES][OUTC / 2];
#pragma unroll
    for (int i = 0; i < NODES; i++) {
        float inv = 1.0f / fmaxf(cnt[node[i]], 1.0f);
#pragma unroll
        for (int c = 0; c < OUTC; c += 4) {
            float4 a = *(const float4*)(agg + (long long)node[i] * OUTC + c);
            acc[i][c / 2]     = pack2f(a.x * inv + sB[c + 0], a.y * inv + sB[c + 1]);
            acc[i][c / 2 + 1] = pack2f(a.z * inv + sB[c + 2], a.w * inv + sB[c + 3]);
        }
    }

#pragma unroll
    for (int kc = 0; kc < INC / 4; kc++) {
        float4 a4[NODES];
#pragma unroll
        for (int i = 0; i < NODES; i++)
            a4[i] = *(const float4*)(in + (long long)node[i] * INC + kc * 4);
#pragma unroll
        for (int j = 0; j < 4; j++) {
            unsigned long long av[NODES];
#pragma unroll
            for (int i = 0; i < NODES; i++) {
                float s = (j == 0 ? a4[i].x : j == 1 ? a4[i].y : j == 2 ? a4[i].z : a4[i].w);
                av[i] = pack2(s);
            }
            const int k = kc * 4 + j;
#pragma unroll
            for (int c = 0; c < OUTC; c += 4) {
                ulonglong2 w2 = *(const ulonglong2*)&sW[k * OUTC + c];
#pragma unroll
                for (int i = 0; i < NODES; i++) {
                    fma2(acc[i][c / 2],     av[i], w2.x);
                    fma2(acc[i][c / 2 + 1], av[i], w2.y);
                }
            }
        }
    }

#pragma unroll
    for (int i = 0; i < NODES; i++) {
        if (!valid[i]) continue;
        float* orow = out + (long long)node[i] * OUTC;
#pragma unroll
        for (int c = 0; c < OUTC; c += 4) {
            float2 p0 = unpack2(acc[i][c / 2]);
            float2 p1 = unpack2(acc[i][c / 2 + 1]);
            float4 o = {p0.x, p0.y, p1.x, p1.y};
            *(float4*)&orow[c] = o;
        }
    }
}

// ---------------------------------------------------------------------------
// Launch
// ---------------------------------------------------------------------------
extern "C" void kernel_launch(void* const* d_in, const int* in_sizes, int n_in,
                              void* d_out, int out_size)
{
    const float* x    = (const float*)d_in[0];
    const int*   ei   = (const int*)d_in[1];
    const float* W1l  = (const float*)d_in[2];
    const float* b1   = (const float*)d_in[3];
    const float* W1r  = (const float*)d_in[4];
    const float* W2l  = (const float*)d_in[5];
    const float* b2   = (const float*)d_in[6];
    const float* W2r  = (const float*)d_in[7];
    float*       out  = (float*)d_out;

    const int n_nodes = in_sizes[0] / IN_C;
    const int n_edges = in_sizes[1] / 2;

    float *agg1, *h, *hw, *agg2, *cnt;
    cudaGetSymbolAddress((void**)&agg1, g_agg1);
    cudaGetSymbolAddress((void**)&h,    g_h);
    cudaGetSymbolAddress((void**)&hw,   g_hw);
    cudaGetSymbolAddress((void**)&agg2, g_agg2);
    cudaGetSymbolAddress((void**)&cnt,  g_cnt);

    cudaMemsetAsync(agg1, 0, (size_t)n_nodes * IN_C  * sizeof(float));
    cudaMemsetAsync(agg2, 0, (size_t)n_nodes * OUT_C * sizeof(float));
    cudaMemsetAsync(cnt,  0, (size_t)n_nodes * sizeof(float));

    const int warps  = (n_edges + 31) / 32;
    const int blocks_sc = (warps * 32 + 255) / 256;

    // Layer 1 aggregate (32-dim) + degree count
    scatter32<true><<<blocks_sc, 256>>>(x, ei, agg1, cnt, n_edges);

    // Fused layer-1 transform (-> h) + pre-projection (-> hw)
    {
        int blocks = (n_nodes + 255) / 256;
        transform_l1_fused<<<blocks, 256>>>(x, agg1, cnt, W1l, b1, W1r, W2l, h, hw, n_nodes);
    }

    // Layer 2 aggregate (32-dim)
    scatter32<false><<<blocks_sc, 256>>>(hw, ei, agg2, nullptr, n_edges);

    // Final: out = agg2/cnt + b2 + h @ W2r
    {
        int blocks = (n_nodes + 1023) / 1024;
        gemm_final<<<blocks, 256>>>(h, W2r, agg2, cnt, b2, out, n_nodes);
    }
}

// round 6
// speedup vs baseline: 2.3464x; 1.0968x over previous
#include <cuda_runtime.h>
#include <cstdint>

#define MAX_NODES 100000
#define IN_C  32
#define HID_C 64
#define OUT_C 32

// Scratch (__device__ globals: allocation-free rule)
__device__ __align__(16) float g_agg1[MAX_NODES * IN_C];    // 12.8 MB
__device__ __align__(16) float g_hw  [MAX_NODES * OUT_C];   // 12.8 MB  relu(h) @ W2_l
__device__ __align__(16) float g_hr  [MAX_NODES * OUT_C];   // 12.8 MB  relu(h) @ W2_r
__device__ __align__(16) float g_agg2[MAX_NODES * OUT_C];   // 12.8 MB
__device__               float g_cnt [MAX_NODES];           // 0.4 MB

// ---------------------------------------------------------------------------
// Packed f32x2 helpers (Blackwell FFMA2)
// ---------------------------------------------------------------------------
__device__ __forceinline__ void fma2(unsigned long long& d,
                                     unsigned long long a,
                                     unsigned long long b)
{
    asm("fma.rn.f32x2 %0, %1, %2, %0;" : "+l"(d) : "l"(a), "l"(b));
}
__device__ __forceinline__ unsigned long long pack2(float v)
{
    unsigned long long r;
    asm("mov.b64 %0, {%1, %1};" : "=l"(r) : "r"(__float_as_uint(v)));
    return r;
}
__device__ __forceinline__ float2 unpack2(unsigned long long v)
{
    float2 f;
    asm("mov.b64 {%0, %1}, %2;" : "=f"(f.x), "=f"(f.y) : "l"(v));
    return f;
}

// ---------------------------------------------------------------------------
// Warp-shuffle scatter-add, C=32. Each warp owns 32 edges: every lane loads
// its own edge's (src,dst) ONCE (coalesced), then 8 passes of 4 edges x 8
// float4 segments; indices distributed via shfl (ALU pipe, off the LSU).
// ---------------------------------------------------------------------------
template <bool COUNT>
__global__ void scatter32(const float* __restrict__ feat,
                          const int* __restrict__ ei,
                          float* __restrict__ agg,
                          float* __restrict__ cnt,
                          int n_edges)
{
    int warp = (blockIdx.x * blockDim.x + threadIdx.x) >> 5;
    int lane = threadIdx.x & 31;
    int base = warp * 32;
    if (base >= n_edges) return;

    int my_e   = base + lane;
    bool has   = my_e < n_edges;
    int e_clmp = has ? my_e : (n_edges - 1);
    int my_src = __ldg(ei + e_clmp);
    int my_dst = __ldg(ei + n_edges + e_clmp);

    if (COUNT && has) atomicAdd(&cnt[my_dst], 1.0f);

    int seg = lane & 7;   // float4 segment within the 32-float row
    int sub = lane >> 3;  // which of 4 edges this pass

#pragma unroll
    for (int pass = 0; pass < 8; pass++) {
        int eslot = pass * 4 + sub;
        int src = __shfl_sync(0xffffffffu, my_src, eslot);
        int dst = __shfl_sync(0xffffffffu, my_dst, eslot);
        if (base + eslot < n_edges) {
            float4 v = *(const float4*)(feat + (long long)src * 32 + seg * 4);
            atomicAdd((float4*)(agg + (long long)dst * 32 + seg * 4), v);
        }
    }
}

// ---------------------------------------------------------------------------
// Fused layer-1 transform + BOTH layer-2 projections:
//   h       = relu( (agg1/max(cnt,1)) @ W1l + b1 + x @ W1r )   (registers only)
//   hw[n,:] = h @ W2l    (scattered 32-dim in layer 2; linearity of mean)
//   hr[n,:] = h @ W2r    (self term of layer 2)
// h is never written to gmem. One node per thread; f32x2 accumulators;
// weights in shared, LDS.128 broadcast.
// ---------------------------------------------------------------------------
__global__ __launch_bounds__(256)
void transform_l1_fused(const float* __restrict__ x,
                        const float* __restrict__ agg,
                        const float* __restrict__ cnt,
                        const float* __restrict__ Wl,
                        const float* __restrict__ b,
                        const float* __restrict__ Wr,
                        const float* __restrict__ W2l,
                        const float* __restrict__ W2r,
                        float* __restrict__ hw,
                        float* __restrict__ hr,
                        int n_nodes)
{
    __shared__ __align__(16) float sWl [IN_C  * HID_C];
    __shared__ __align__(16) float sWr [IN_C  * HID_C];
    __shared__ __align__(16) float sW2l[HID_C * OUT_C];
    __shared__ __align__(16) float sW2r[HID_C * OUT_C];
    __shared__ float sB[HID_C];

    for (int i = threadIdx.x * 4; i < IN_C * HID_C; i += 256 * 4) {
        *(float4*)&sWl[i] = *(const float4*)&Wl[i];
        *(float4*)&sWr[i] = *(const float4*)&Wr[i];
    }
    for (int i = threadIdx.x * 4; i < HID_C * OUT_C; i += 256 * 4) {
        *(float4*)&sW2l[i] = *(const float4*)&W2l[i];
        *(float4*)&sW2r[i] = *(const float4*)&W2r[i];
    }
    if (threadIdx.x < HID_C) sB[threadIdx.x] = b[threadIdx.x];
    __syncthreads();

    int node = blockIdx.x * 256 + threadIdx.x;
    if (node >= n_nodes) return;

    float inv = 1.0f / fmaxf(cnt[node], 1.0f);

    unsigned long long acc[HID_C / 2];
#pragma unroll
    for (int i = 0; i < HID_C / 2; i++) acc[i] = 0ull;

    // Pass 1: (agg/cnt) @ W1l
    {
        const float4* arow = (const float4*)(agg + (long long)node * IN_C);
#pragma unroll
        for (int kc = 0; kc < IN_C / 4; kc++) {
            float4 a4 = arow[kc];
            float av[4] = {a4.x * inv, a4.y * inv, a4.z * inv, a4.w * inv};
#pragma unroll
            for (int j = 0; j < 4; j++) {
                unsigned long long av2 = pack2(av[j]);
                const int k = kc * 4 + j;
#pragma unroll
                for (int c = 0; c < HID_C; c += 4) {
                    ulonglong2 w2 = *(const ulonglong2*)&sWl[k * HID_C + c];
                    fma2(acc[c / 2],     av2, w2.x);
                    fma2(acc[c / 2 + 1], av2, w2.y);
                }
            }
        }
    }
    // Pass 2: x @ W1r
    {
        const float4* xrow = (const float4*)(x + (long long)node * IN_C);
#pragma unroll
        for (int kc = 0; kc < IN_C / 4; kc++) {
            float4 a4 = xrow[kc];
            float av[4] = {a4.x, a4.y, a4.z, a4.w};
#pragma unroll
            for (int j = 0; j < 4; j++) {
                unsigned long long av2 = pack2(av[j]);
                const int k = kc * 4 + j;
#pragma unroll
                for (int c = 0; c < HID_C; c += 4) {
                    ulonglong2 w2 = *(const ulonglong2*)&sWr[k * HID_C + c];
                    fma2(acc[c / 2],     av2, w2.x);
                    fma2(acc[c / 2 + 1], av2, w2.y);
                }
            }
        }
    }

    // Bias + ReLU -> h in registers only
    float hval[HID_C];
#pragma unroll
    for (int c = 0; c < HID_C; c += 2) {
        float2 p = unpack2(acc[c / 2]);
        hval[c + 0] = fmaxf(p.x + sB[c + 0], 0.0f);
        hval[c + 1] = fmaxf(p.y + sB[c + 1], 0.0f);
    }

    // Pass 3+4: hw = h @ W2l, hr = h @ W2r (shared av broadcast per k)
    unsigned long long accL[OUT_C / 2], accR[OUT_C / 2];
#pragma unroll
    for (int i = 0; i < OUT_C / 2; i++) { accL[i] = 0ull; accR[i] = 0ull; }
#pragma unroll
    for (int k = 0; k < HID_C; k++) {
        unsigned long long av2 = pack2(hval[k]);
#pragma unroll
        for (int c = 0; c < OUT_C; c += 4) {
            ulonglong2 wl = *(const ulonglong2*)&sW2l[k * OUT_C + c];
            fma2(accL[c / 2],     av2, wl.x);
            fma2(accL[c / 2 + 1], av2, wl.y);
            ulonglong2 wr = *(const ulonglong2*)&sW2r[k * OUT_C + c];
            fma2(accR[c / 2],     av2, wr.x);
            fma2(accR[c / 2 + 1], av2, wr.y);
        }
    }
    float* hwrow = hw + (long long)node * OUT_C;
    float* hrrow = hr + (long long)node * OUT_C;
#pragma unroll
    for (int c = 0; c < OUT_C; c += 4) {
        float2 l0 = unpack2(accL[c / 2]);
        float2 l1 = unpack2(accL[c / 2 + 1]);
        float4 ol = {l0.x, l0.y, l1.x, l1.y};
        *(float4*)&hwrow[c] = ol;
        float2 r0 = unpack2(accR[c / 2]);
        float2 r1 = unpack2(accR[c / 2 + 1]);
        float4 orr = {r0.x, r0.y, r1.x, r1.y};
        *(float4*)&hrrow[c] = orr;
    }
}

// ---------------------------------------------------------------------------
// Final elementwise: out[n,c] = agg2[n,c]/max(cnt[n],1) + b2[c] + hr[n,c]
// One float4 per thread; streaming, high occupancy.
// ---------------------------------------------------------------------------
__global__ __launch_bounds__(256)
void final_add(const float* __restrict__ agg,
               const float* __restrict__ cnt,
               const float* __restrict__ b,
               const float* __restrict__ hr,
               float* __restrict__ out,
               int n_nodes)
{
    __shared__ float sB[OUT_C];
    if (threadIdx.x < OUT_C) sB[threadIdx.x] = b[threadIdx.x];
    __syncthreads();

    int t = blockIdx.x * 256 + threadIdx.x;          // one float4 slot
    int total = n_nodes * (OUT_C / 4);
    if (t >= total) return;

    int node = t >> 3;       // OUT_C/4 = 8 slots per node
    int seg  = t & 7;

    float inv = 1.0f / fmaxf(cnt[node], 1.0f);
    float4 a = *(const float4*)(agg + (long long)node * OUT_C + seg * 4);
    float4 r = *(const float4*)(hr  + (long long)node * OUT_C + seg * 4);
    float4 o;
    o.x = a.x * inv + sB[seg * 4 + 0] + r.x;
    o.y = a.y * inv + sB[seg * 4 + 1] + r.y;
    o.z = a.z * inv + sB[seg * 4 + 2] + r.z;
    o.w = a.w * inv + sB[seg * 4 + 3] + r.w;
    *(float4*)(out + (long long)node * OUT_C + seg * 4) = o;
}

// ---------------------------------------------------------------------------
// Launch
// ---------------------------------------------------------------------------
extern "C" void kernel_launch(void* const* d_in, const int* in_sizes, int n_in,
                              void* d_out, int out_size)
{
    const float* x    = (const float*)d_in[0];
    const int*   ei   = (const int*)d_in[1];
    const float* W1l  = (const float*)d_in[2];
    const float* b1   = (const float*)d_in[3];
    const float* W1r  = (const float*)d_in[4];
    const float* W2l  = (const float*)d_in[5];
    const float* b2   = (const float*)d_in[6];
    const float* W2r  = (const float*)d_in[7];
    float*       out  = (float*)d_out;

    const int n_nodes = in_sizes[0] / IN_C;
    const int n_edges = in_sizes[1] / 2;

    float *agg1, *hw, *hr, *agg2, *cnt;
    cudaGetSymbolAddress((void**)&agg1, g_agg1);
    cudaGetSymbolAddress((void**)&hw,   g_hw);
    cudaGetSymbolAddress((void**)&hr,   g_hr);
    cudaGetSymbolAddress((void**)&agg2, g_agg2);
    cudaGetSymbolAddress((void**)&cnt,  g_cnt);

    cudaMemsetAsync(agg1, 0, (size_t)n_nodes * IN_C  * sizeof(float));
    cudaMemsetAsync(agg2, 0, (size_t)n_nodes * OUT_C * sizeof(float));
    cudaMemsetAsync(cnt,  0, (size_t)n_nodes * sizeof(float));

    const int warps  = (n_edges + 31) / 32;
    const int blocks_sc = (warps * 32 + 255) / 256;

    // Layer 1 aggregate (32-dim) + degree count
    scatter32<true><<<blocks_sc, 256>>>(x, ei, agg1, cnt, n_edges);

    // Fused: layer-1 transform + hw (=h@W2l) + hr (=h@W2r); h stays in regs
    {
        int blocks = (n_nodes + 255) / 256;
        transform_l1_fused<<<blocks, 256>>>(x, agg1, cnt, W1l, b1, W1r,
                                            W2l, W2r, hw, hr, n_nodes);
    }

    // Layer 2 aggregate (32-dim)
    scatter32<false><<<blocks_sc, 256>>>(hw, ei, agg2, nullptr, n_edges);

    // Final elementwise combine
    {
        int total = n_nodes * (OUT_C / 4);
        int blocks = (total + 255) / 256;
        final_add<<<blocks, 256>>>(agg2, cnt, b2, hr, out, n_nodes);
    }
}